// round 1
// baseline (speedup 1.0000x reference)
#include <cuda_runtime.h>

// Problem dims (fixed by reference)
static constexpr int BATCH = 4;
static constexpr int SEQ   = 2048;
static constexpr int DIM   = 1024;

// Scratch for Q, K, V projections (device globals: allocation-guard safe)
__device__ float g_q[BATCH * SEQ * DIM];
__device__ float g_k[BATCH * SEQ * DIM];
__device__ float g_v[BATCH * SEQ * DIM];

// ---------------------------------------------------------------------------
// Generic tiled fp32 GEMM.
//   C = alpha * A @ op(B) (+ bias)
//   A: [M,K] row-major.
//   BT=true : B stored [N,K] (i.e. compute A @ B^T)   -- QKV proj, Q@K^T
//   BT=false: B stored [K,N]                          -- AW @ V
// Batched via blockIdx.z with element strides sA/sB/sC.
// Tile: 64x64 output, K-step 16, 256 threads, 4x4 microtile per thread.
// All problem dims here are multiples of 64/16 -> no edge handling.
// ---------------------------------------------------------------------------
template <bool BT>
__global__ __launch_bounds__(256)
void gemm_kernel(const float* __restrict__ A,
                 const float* __restrict__ Bm,
                 const float* __restrict__ bias,
                 float* __restrict__ C,
                 int M, int N, int K, float alpha,
                 long sA, long sB, long sC)
{
    __shared__ float As[16][68];   // [k][m], 68 -> rows 16B-aligned for float4
    __shared__ float Bs[16][64];   // [k][n]

    const float* Ab = A  + (long)blockIdx.z * sA;
    const float* Bb = Bm + (long)blockIdx.z * sB;
    float*       Cb = C  + (long)blockIdx.z * sC;

    const int m0  = blockIdx.y * 64;
    const int n0  = blockIdx.x * 64;
    const int tid = threadIdx.x;
    const int tx  = tid & 15;        // microtile col group
    const int ty  = tid >> 4;        // microtile row group

    const int lrow = tid >> 2;        // 0..63  (A / B^T tile row)
    const int lcol = (tid & 3) << 2;  // 0,4,8,12 (k offset)
    const int brow = tid >> 4;        // 0..15  (B [K,N] tile row)
    const int bcol = (tid & 15) << 2; // 0..60

    float acc[4][4] = {};

    for (int k0 = 0; k0 < K; k0 += 16) {
        // Load A tile 64x16 (coalesced float4), store transposed As[k][m]
        float4 a4 = *(const float4*)(Ab + (long)(m0 + lrow) * K + k0 + lcol);
        As[lcol + 0][lrow] = a4.x;
        As[lcol + 1][lrow] = a4.y;
        As[lcol + 2][lrow] = a4.z;
        As[lcol + 3][lrow] = a4.w;

        if (BT) {
            // B [N,K]: same pattern as A
            float4 b4 = *(const float4*)(Bb + (long)(n0 + lrow) * K + k0 + lcol);
            Bs[lcol + 0][lrow] = b4.x;
            Bs[lcol + 1][lrow] = b4.y;
            Bs[lcol + 2][lrow] = b4.z;
            Bs[lcol + 3][lrow] = b4.w;
        } else {
            // B [K,N]: 16x64 tile, direct copy
            float4 b4 = *(const float4*)(Bb + (long)(k0 + brow) * N + n0 + bcol);
            *(float4*)&Bs[brow][bcol] = b4;
        }
        __syncthreads();

        #pragma unroll
        for (int k = 0; k < 16; ++k) {
            float4 av = *(const float4*)&As[k][ty << 2];
            float4 bv = *(const float4*)&Bs[k][tx << 2];
            float ar[4] = {av.x, av.y, av.z, av.w};
            float br[4] = {bv.x, bv.y, bv.z, bv.w};
            #pragma unroll
            for (int i = 0; i < 4; ++i)
                #pragma unroll
                for (int j = 0; j < 4; ++j)
                    acc[i][j] = fmaf(ar[i], br[j], acc[i][j]);
        }
        __syncthreads();
    }

    #pragma unroll
    for (int i = 0; i < 4; ++i) {
        const int m = m0 + (ty << 2) + i;
        #pragma unroll
        for (int j = 0; j < 4; ++j) {
            const int n = n0 + (tx << 2) + j;
            float v = acc[i][j] * alpha;
            if (bias) v += bias[n];
            Cb[(long)m * N + n] = v;
        }
    }
}

// ---------------------------------------------------------------------------
// In-place row softmax. One 256-thread block per row of 2048 elements.
// Values held in registers: one global load + one global store per element.
// ---------------------------------------------------------------------------
__global__ __launch_bounds__(256)
void softmax_kernel(float* __restrict__ data)
{
    constexpr int NC = SEQ;        // 2048
    constexpr int PT = NC / 256;   // 8 per thread

    float* row = data + (long)blockIdx.x * NC;
    __shared__ float red[8];

    const int tid  = threadIdx.x;
    const int lane = tid & 31;
    const int warp = tid >> 5;

    float v[PT];
    #pragma unroll
    for (int i = 0; i < PT; ++i) v[i] = row[tid + i * 256];

    // --- max reduce ---
    float lmax = v[0];
    #pragma unroll
    for (int i = 1; i < PT; ++i) lmax = fmaxf(lmax, v[i]);
    #pragma unroll
    for (int o = 16; o > 0; o >>= 1)
        lmax = fmaxf(lmax, __shfl_xor_sync(0xFFFFFFFFu, lmax, o));
    if (lane == 0) red[warp] = lmax;
    __syncthreads();
    float rmax = red[0];
    #pragma unroll
    for (int w = 1; w < 8; ++w) rmax = fmaxf(rmax, red[w]);
    __syncthreads();

    // --- exp + sum reduce ---
    float lsum = 0.0f;
    #pragma unroll
    for (int i = 0; i < PT; ++i) {
        v[i] = __expf(v[i] - rmax);
        lsum += v[i];
    }
    #pragma unroll
    for (int o = 16; o > 0; o >>= 1)
        lsum += __shfl_xor_sync(0xFFFFFFFFu, lsum, o);
    if (lane == 0) red[warp] = lsum;
    __syncthreads();
    float rsum = 0.0f;
    #pragma unroll
    for (int w = 0; w < 8; ++w) rsum += red[w];

    const float inv = 1.0f / rsum;
    #pragma unroll
    for (int i = 0; i < PT; ++i) row[tid + i * 256] = v[i] * inv;
}

// ---------------------------------------------------------------------------
// Launch: QKV proj -> scores -> softmax -> AV
// Output layout (tuple order): [weighted_sum B*S*D | attention_weights B*S*S]
// ---------------------------------------------------------------------------
extern "C" void kernel_launch(void* const* d_in, const int* in_sizes, int n_in,
                              void* d_out, int out_size)
{
    const float* x  = (const float*)d_in[0];
    const float* Wq = (const float*)d_in[1];
    const float* bq = (const float*)d_in[2];
    const float* Wk = (const float*)d_in[3];
    const float* bk = (const float*)d_in[4];
    const float* Wv = (const float*)d_in[5];
    const float* bv = (const float*)d_in[6];

    float* out_ws = (float*)d_out;                                  // [B,S,D]
    float* out_aw = (float*)d_out + (long)BATCH * SEQ * DIM;        // [B,S,S]

    float *q, *k, *v;
    cudaGetSymbolAddress((void**)&q, g_q);
    cudaGetSymbolAddress((void**)&k, g_k);
    cudaGetSymbolAddress((void**)&v, g_v);

    const dim3 blk(256);

    // 1) QKV projections: M = B*S = 8192, N = K = 1024, A@B^T + bias
    {
        dim3 grid(DIM / 64, (BATCH * SEQ) / 64, 1);
        gemm_kernel<true><<<grid, blk>>>(x, Wq, bq, q, BATCH * SEQ, DIM, DIM,
                                         1.0f, 0, 0, 0);
        gemm_kernel<true><<<grid, blk>>>(x, Wk, bk, k, BATCH * SEQ, DIM, DIM,
                                         1.0f, 0, 0, 0);
        gemm_kernel<true><<<grid, blk>>>(x, Wv, bv, v, BATCH * SEQ, DIM, DIM,
                                         1.0f, 0, 0, 0);
    }

    // 2) scores = (Q @ K^T) / sqrt(D), batched, written into attn-weight region
    {
        dim3 grid(SEQ / 64, SEQ / 64, BATCH);
        gemm_kernel<true><<<grid, blk>>>(q, k, nullptr, out_aw, SEQ, SEQ, DIM,
                                         0.03125f,
                                         (long)SEQ * DIM, (long)SEQ * DIM,
                                         (long)SEQ * SEQ);
    }

    // 3) row softmax in place on attention weights
    softmax_kernel<<<BATCH * SEQ, blk>>>(out_aw);

    // 4) weighted_sum = AW @ V  (B stored [K=S, N=D], non-transposed)
    {
        dim3 grid(DIM / 64, SEQ / 64, BATCH);
        gemm_kernel<false><<<grid, blk>>>(out_aw, v, nullptr, out_ws, SEQ, DIM,
                                          SEQ, 1.0f,
                                          (long)SEQ * SEQ, (long)SEQ * DIM,
                                          (long)SEQ * DIM);
    }
}